// round 12
// baseline (speedup 1.0000x reference)
#include <cuda_runtime.h>
#include <cuda_fp16.h>
#include <cstdint>

// ============================================================================
// Problem: x [8,256,16384] fp32, params [8,512], W [256,512]  ->  out fp32
// Rewrite: out[b,o,p] = sum_i G[b,o,i]*xh[b,i,p] + bias2[b,o]
// R12: R11 structure + L2 hygiene (__ldcs on dead x stream, __stcs on
// write-once out stream) so xh stays L2-resident between stats and gemm.
// ============================================================================
#define NB   8
#define NC   256
#define NHW  16384

__device__ __align__(1024) __half  g_xh[NB * NC * NHW];   // fp16(x)
__device__ __align__(1024) __half  g_G[NB * NC * NC];     // fused weight fp16
__device__ float2 g_partial[NB * NC];                     // per (b,c) sum/sumsq
__device__ float  g_bias2[NB * NC];

__device__ __forceinline__ uint32_t smem_u32(const void* p) {
    uint32_t a;
    asm("{ .reg .u64 t; cvta.to.shared.u64 t, %1; cvt.u32.u64 %0, t; }"
        : "=r"(a) : "l"(p));
    return a;
}

__device__ __forceinline__ void cp_async16(uint32_t dst, const void* src) {
    asm volatile("cp.async.cg.shared.global [%0], [%1], 16;"
                 :: "r"(dst), "l"(src) : "memory");
}
__device__ __forceinline__ void cp_commit() {
    asm volatile("cp.async.commit_group;" ::: "memory");
}
template <int N>
__device__ __forceinline__ void cp_wait() {
    asm volatile("cp.async.wait_group %0;" :: "n"(N) : "memory");
}

__device__ __forceinline__ void ldm_x4(uint32_t (&r)[4], uint32_t addr) {
    asm volatile("ldmatrix.sync.aligned.m8n8.x4.shared.b16 {%0,%1,%2,%3}, [%4];"
                 : "=r"(r[0]), "=r"(r[1]), "=r"(r[2]), "=r"(r[3]) : "r"(addr));
}
__device__ __forceinline__ void ldm_x4_t(uint32_t (&r)[4], uint32_t addr) {
    asm volatile("ldmatrix.sync.aligned.m8n8.x4.trans.shared.b16 {%0,%1,%2,%3}, [%4];"
                 : "=r"(r[0]), "=r"(r[1]), "=r"(r[2]), "=r"(r[3]) : "r"(addr));
}
__device__ __forceinline__ void mma16816(float (&c)[4], const uint32_t a0,
                                         const uint32_t a1, const uint32_t a2,
                                         const uint32_t a3,
                                         uint32_t b0, uint32_t b1) {
    asm volatile(
        "mma.sync.aligned.m16n8k16.row.col.f32.f16.f16.f32 "
        "{%0,%1,%2,%3}, {%4,%5,%6,%7}, {%8,%9}, {%0,%1,%2,%3};"
        : "+f"(c[0]), "+f"(c[1]), "+f"(c[2]), "+f"(c[3])
        : "r"(a0), "r"(a1), "r"(a2), "r"(a3), "r"(b0), "r"(b1));
}

// streaming (evict-first) load of float4
__device__ __forceinline__ float4 ldcs_f4(const float4* p) {
    float4 v;
    asm volatile("ld.global.cs.v4.f32 {%0,%1,%2,%3}, [%4];"
                 : "=f"(v.x), "=f"(v.y), "=f"(v.z), "=f"(v.w) : "l"(p));
    return v;
}
// streaming (evict-first) store of float2
__device__ __forceinline__ void stcs_f2(float2* p, float2 v) {
    asm volatile("st.global.cs.v2.f32 [%0], {%1,%2};"
                 :: "l"(p), "f"(v.x), "f"(v.y) : "memory");
}

// ============================================================================
// Kernel 1: per-(b,c) sum/sumsq over HW + fp16(RN) conversion (fused pass).
// x is read with .cs (dead after this pass) so the xh writes own L2.
// ============================================================================
__global__ void __launch_bounds__(256) stats_convert(const float* __restrict__ x) {
    int bc = blockIdx.x;
    int t = threadIdx.x;
    const float4* xin = reinterpret_cast<const float4*>(x) + (size_t)bc * 4096;
    uint2* xout = reinterpret_cast<uint2*>(g_xh) + (size_t)bc * 4096;
    float s = 0.f, ss = 0.f;
#pragma unroll
    for (int i = 0; i < 16; i++) {
        float4 v = ldcs_f4(&xin[i * 256 + t]);
        s  += (v.x + v.y) + (v.z + v.w);
        ss += v.x * v.x + v.y * v.y + v.z * v.z + v.w * v.w;
        __half2 h0 = __floats2half2_rn(v.x, v.y);
        __half2 h1 = __floats2half2_rn(v.z, v.w);
        uint2 u;
        u.x = *reinterpret_cast<uint32_t*>(&h0);
        u.y = *reinterpret_cast<uint32_t*>(&h1);
        xout[i * 256 + t] = u;
    }
    __shared__ float s1[256], s2[256];
    s1[t] = s; s2[t] = ss;
    __syncthreads();
    for (int st = 128; st > 0; st >>= 1) {
        if (t < st) { s1[t] += s1[t + st]; s2[t] += s2[t + st]; }
        __syncthreads();
    }
    if (t == 0) g_partial[bc] = make_float2(s1[0], s2[0]);
}

// ============================================================================
// Kernel 2: build fused weight G[b,o,i] (fp16) and bias2[b,o].
// Finalize folded in: each block re-derives r/mu from g_partial (L2-hot).
// ============================================================================
__global__ void __launch_bounds__(256) prep_kernel(const float* __restrict__ params,
                                                   const float* __restrict__ W) {
    int bo = blockIdx.x;
    int b = bo >> 8, o = bo & 255, i = threadIdx.x;

    float2 p = g_partial[b * NC + i];
    const float invN = 1.0f / (float)NHW;
    float mu_i = p.x * invN;
    float var_i = fmaxf(p.y * invN - mu_i * mu_i, 0.f);
    float r_i = rsqrtf(var_i + 1e-5f);

    __shared__ float s1[256], s2[256];
    s1[i] = p.x; s2[i] = p.y;
    __syncthreads();
    for (int st = 128; st > 0; st >>= 1) {
        if (i < st) { s1[i] += s1[i + st]; s2[i] += s2[i + st]; }
        __syncthreads();
    }
    const float invM = 1.0f / ((float)NHW * (float)NC);
    float mub = s1[0] * invM;
    float vb = fmaxf(s2[0] * invM - mub * mub, 0.f);
    float rb = rsqrtf(vb + 1e-5f);
    __syncthreads();

    float w1 = W[o * 512 + i];
    float w2 = W[o * 512 + 256 + i];
    float gamma = params[b * 512 + o];
    g_G[(size_t)bo * NC + i] = __float2half_rn(gamma * (w1 * r_i + w2 * rb));
    float cp = w1 * r_i * mu_i + rb * mub * w2;
    s1[i] = cp;
    __syncthreads();
    for (int st = 128; st > 0; st >>= 1) {
        if (i < st) s1[i] += s1[i + st];
        __syncthreads();
    }
    if (i == 0) {
        float beta = params[b * 512 + 256 + o];
        g_bias2[bo] = beta - gamma * s1[0];
    }
}

// ============================================================================
// Kernel 3: HMMA GEMM — R5/R11 configuration (empirical optimum):
// 2 CTAs/SM, 256 threads, M=128 x N=128px x K=256, warp grid 4(M)x2(N),
// warp tile 32x64, 3-stage cp.async ring, one __syncthreads per 32-k chunk.
// mz fastest so CTA pairs sharing a pixel tile run concurrently (X via L2).
// out stored with .cs so the write-once stream doesn't evict xh from L2.
// ============================================================================
#define A_ROWS     128
#define A_STRIDE_H 264              // halves per A row (256 + 8 pad)
#define X_STRIDE_H 136              // halves per X row (128 + 8 pad)
#define KCHUNK     32
#define NCHUNKS    8
#define NSTAGES    3
#define A_BYTES    (A_ROWS * A_STRIDE_H * 2)           // 67584
#define X_BUF_BYTES (KCHUNK * X_STRIDE_H * 2)          // 8704
#define GEMM_SMEM  (A_BYTES + NSTAGES * X_BUF_BYTES)   // 93696

__global__ void __launch_bounds__(256, 2) gemm_kernel(float* __restrict__ out) {
    extern __shared__ char smem[];
    const uint32_t Asm = smem_u32(smem);
    const uint32_t Xsm = Asm + A_BYTES;

    const int tid = threadIdx.x;
    const int lane = tid & 31, wid = tid >> 5;
    const int warpM = (wid & 3) * 32;          // 4 warps over M=128
    const int warpN = (wid >> 2) * 64;         // 2 warps over N=128
    const int b = blockIdx.y;
    const int mz = blockIdx.x & 1;             // fastest dim: M half
    const int px0 = (blockIdx.x >> 1) * 128;

    // X chunk loader: 32 rows x 256B; 256 threads -> 2 x 16B each
    const int xr = tid >> 4, xseg = tid & 15;
    const __half* xbase = g_xh + ((size_t)(b * NC + xr)) * NHW + px0 + xseg * 8;
    const uint32_t xdst0 = Xsm + xr * (X_STRIDE_H * 2) + xseg * 16;
    const size_t xrow16 = (size_t)16 * NHW;

    // ---- prologue: A + chunks 0,1 ----
    {
        const __half* gsrc = g_G + (size_t)b * NC * NC + (size_t)mz * 128 * NC;
#pragma unroll
        for (int i = 0; i < 16; i++) {
            int c = tid + i * 256;
            int row = c >> 5, seg = c & 31;
            cp_async16(Asm + row * (A_STRIDE_H * 2) + seg * 16,
                       gsrc + row * 256 + seg * 8);
        }
        cp_async16(xdst0, xbase);
        cp_async16(xdst0 + 16 * (X_STRIDE_H * 2), xbase + xrow16);
        cp_commit();                                   // group: A + chunk0
        cp_async16(xdst0 + X_BUF_BYTES, xbase + (size_t)KCHUNK * NHW);
        cp_async16(xdst0 + X_BUF_BYTES + 16 * (X_STRIDE_H * 2),
                   xbase + (size_t)KCHUNK * NHW + xrow16);
        cp_commit();                                   // group: chunk1
    }

    float acc[2][8][4];
#pragma unroll
    for (int mi = 0; mi < 2; mi++)
#pragma unroll
        for (int ni = 0; ni < 8; ni++)
#pragma unroll
            for (int j = 0; j < 4; j++) acc[mi][ni][j] = 0.f;

    const int lrow = (lane & 7) + ((lane >> 3) & 1) * 8;   // 0..15
    const int lcol8 = (lane >> 4) * 8;                      // 0 or 8
    const int xlrow = ((lane >> 3) & 1) * 8 + (lane & 7);   // B-frag k row

    for (int kc = 0; kc < NCHUNKS; kc++) {
        cp_wait<1>();          // this thread's chunk-kc copies complete
        __syncthreads();       // cross-thread visibility + ring safety

        if (kc + 2 < NCHUNKS) {    // prefetch kc+2 into slot (kc+2)%3
            uint32_t d = xdst0 + ((kc + 2) % NSTAGES) * X_BUF_BYTES;
            const __half* s = xbase + (size_t)(kc + 2) * KCHUNK * NHW;
            cp_async16(d, s);
            cp_async16(d + 16 * (X_STRIDE_H * 2), s + xrow16);
        }
        cp_commit();

        const uint32_t xbuf = Xsm + (kc % NSTAGES) * X_BUF_BYTES;
#pragma unroll
        for (int ks = 0; ks < 2; ks++) {
            const int kbase = kc * KCHUNK + ks * 16;
            uint32_t af[2][4];
#pragma unroll
            for (int mi = 0; mi < 2; mi++) {
                uint32_t addr = Asm
                    + (warpM + mi * 16 + lrow) * (A_STRIDE_H * 2)
                    + (kbase + lcol8) * 2;
                ldm_x4(af[mi], addr);
            }
            uint32_t bf[8][2];
#pragma unroll
            for (int np = 0; np < 4; np++) {
                uint32_t r4[4];
                uint32_t addr = xbuf
                    + (ks * 16 + xlrow) * (X_STRIDE_H * 2)
                    + (warpN + np * 16 + lcol8) * 2;
                ldm_x4_t(r4, addr);
                bf[np * 2 + 0][0] = r4[0]; bf[np * 2 + 0][1] = r4[1];
                bf[np * 2 + 1][0] = r4[2]; bf[np * 2 + 1][1] = r4[3];
            }
#pragma unroll
            for (int mi = 0; mi < 2; mi++)
#pragma unroll
                for (int ni = 0; ni < 8; ni++)
                    mma16816(acc[mi][ni], af[mi][0], af[mi][1], af[mi][2],
                             af[mi][3], bf[ni][0], bf[ni][1]);
        }
    }

    // ---- epilogue: add bias2, streaming store fp32 ----
#pragma unroll
    for (int mi = 0; mi < 2; mi++) {
        int chl = mz * 128 + warpM + mi * 16 + (lane >> 2);
        float bias0 = g_bias2[b * NC + chl];
        float bias1 = g_bias2[b * NC + chl + 8];
        float* row0 = out + ((size_t)(b * NC + chl)) * NHW + px0 + warpN;
        float* row1 = row0 + (size_t)8 * NHW;
#pragma unroll
        for (int ni = 0; ni < 8; ni++) {
            int co = ni * 8 + (lane & 3) * 2;
            float2 v0 = make_float2(acc[mi][ni][0] + bias0, acc[mi][ni][1] + bias0);
            float2 v1 = make_float2(acc[mi][ni][2] + bias1, acc[mi][ni][3] + bias1);
            stcs_f2(reinterpret_cast<float2*>(row0 + co), v0);
            stcs_f2(reinterpret_cast<float2*>(row1 + co), v1);
        }
    }
}

// ============================================================================
// Host
// ============================================================================
extern "C" void kernel_launch(void* const* d_in, const int* in_sizes, int n_in,
                              void* d_out, int out_size) {
    const float* x = (const float*)d_in[0];
    const float* params = (const float*)d_in[1];
    const float* W = (const float*)d_in[2];
    float* out = (float*)d_out;

    stats_convert<<<NB * NC, 256>>>(x);
    prep_kernel<<<NB * NC, 256>>>(params, W);

    cudaFuncSetAttribute(gemm_kernel,
                         cudaFuncAttributeMaxDynamicSharedMemorySize, GEMM_SMEM);
    gemm_kernel<<<dim3(2 * (NHW / 128), NB), 256, GEMM_SMEM>>>(out);
}

// round 15
// speedup vs baseline: 1.0233x; 1.0233x over previous
#include <cuda_runtime.h>
#include <cuda_fp16.h>
#include <cstdint>

// ============================================================================
// Problem: x [8,256,16384] fp32, params [8,512], W [256,512]  ->  out fp32
// Rewrite: out[b,o,p] = sum_i G[b,o,i]*xh[b,i,p] + bias2[b,o]
// R15 = R13 design, third submit (two infra failures): R11 structure (proven
// optimum, 112.6us) + stats_convert rebuilt for MLP (4-wide load batches).
// Hedge vs possible toolchain issue: min-blocks clause dropped from
// stats launch bounds (default reg budget suffices for the batching).
// ============================================================================
#define NB   8
#define NC   256
#define NHW  16384

__device__ __align__(1024) __half  g_xh[NB * NC * NHW];   // fp16(x)
__device__ __align__(1024) __half  g_G[NB * NC * NC];     // fused weight fp16
__device__ float2 g_partial[NB * NC];                     // per (b,c) sum/sumsq
__device__ float  g_bias2[NB * NC];

__device__ __forceinline__ uint32_t smem_u32(const void* p) {
    uint32_t a;
    asm("{ .reg .u64 t; cvta.to.shared.u64 t, %1; cvt.u32.u64 %0, t; }"
        : "=r"(a) : "l"(p));
    return a;
}

__device__ __forceinline__ void cp_async16(uint32_t dst, const void* src) {
    asm volatile("cp.async.cg.shared.global [%0], [%1], 16;"
                 :: "r"(dst), "l"(src) : "memory");
}
__device__ __forceinline__ void cp_commit() {
    asm volatile("cp.async.commit_group;" ::: "memory");
}
template <int N>
__device__ __forceinline__ void cp_wait() {
    asm volatile("cp.async.wait_group %0;" :: "n"(N) : "memory");
}

__device__ __forceinline__ void ldm_x4(uint32_t (&r)[4], uint32_t addr) {
    asm volatile("ldmatrix.sync.aligned.m8n8.x4.shared.b16 {%0,%1,%2,%3}, [%4];"
                 : "=r"(r[0]), "=r"(r[1]), "=r"(r[2]), "=r"(r[3]) : "r"(addr));
}
__device__ __forceinline__ void ldm_x4_t(uint32_t (&r)[4], uint32_t addr) {
    asm volatile("ldmatrix.sync.aligned.m8n8.x4.trans.shared.b16 {%0,%1,%2,%3}, [%4];"
                 : "=r"(r[0]), "=r"(r[1]), "=r"(r[2]), "=r"(r[3]) : "r"(addr));
}
__device__ __forceinline__ void mma16816(float (&c)[4], const uint32_t a0,
                                         const uint32_t a1, const uint32_t a2,
                                         const uint32_t a3,
                                         uint32_t b0, uint32_t b1) {
    asm volatile(
        "mma.sync.aligned.m16n8k16.row.col.f32.f16.f16.f32 "
        "{%0,%1,%2,%3}, {%4,%5,%6,%7}, {%8,%9}, {%0,%1,%2,%3};"
        : "+f"(c[0]), "+f"(c[1]), "+f"(c[2]), "+f"(c[3])
        : "r"(a0), "r"(a1), "r"(a2), "r"(a3), "r"(b0), "r"(b1));
}

// ============================================================================
// Kernel 1: per-(b,c) sum/sumsq over HW + fp16(RN) conversion.
// 4-wide independent load batches raise MLP_eff (R11 variant was regs=32,
// MLP~2, DRAM 70%).  Default reg budget (no min-blocks clause).
// ============================================================================
__global__ void __launch_bounds__(256) stats_convert(const float* __restrict__ x) {
    int bc = blockIdx.x;
    int t = threadIdx.x;
    const float4* xin = reinterpret_cast<const float4*>(x) + (size_t)bc * 4096;
    uint2* xout = reinterpret_cast<uint2*>(g_xh) + (size_t)bc * 4096;
    float s = 0.f, ss = 0.f;
#pragma unroll
    for (int j = 0; j < 4; j++) {
        // batch of 4 independent float4 loads (16 data regs live at once)
        float4 v0 = xin[(j * 4 + 0) * 256 + t];
        float4 v1 = xin[(j * 4 + 1) * 256 + t];
        float4 v2 = xin[(j * 4 + 2) * 256 + t];
        float4 v3 = xin[(j * 4 + 3) * 256 + t];
#pragma unroll
        for (int q = 0; q < 4; q++) {
            float4 v = (q == 0) ? v0 : (q == 1) ? v1 : (q == 2) ? v2 : v3;
            s  += (v.x + v.y) + (v.z + v.w);
            ss += v.x * v.x + v.y * v.y + v.z * v.z + v.w * v.w;
            __half2 h0 = __floats2half2_rn(v.x, v.y);
            __half2 h1 = __floats2half2_rn(v.z, v.w);
            uint2 u;
            u.x = *reinterpret_cast<uint32_t*>(&h0);
            u.y = *reinterpret_cast<uint32_t*>(&h1);
            xout[(j * 4 + q) * 256 + t] = u;
        }
    }
    // warp shuffle reduce, then one smem round over 8 warp partials
#pragma unroll
    for (int off = 16; off > 0; off >>= 1) {
        s  += __shfl_xor_sync(0xFFFFFFFFu, s,  off);
        ss += __shfl_xor_sync(0xFFFFFFFFu, ss, off);
    }
    __shared__ float ws[8], wss[8];
    int lane = t & 31, wid = t >> 5;
    if (lane == 0) { ws[wid] = s; wss[wid] = ss; }
    __syncthreads();
    if (t == 0) {
        float a = 0.f, b2 = 0.f;
#pragma unroll
        for (int w = 0; w < 8; w++) { a += ws[w]; b2 += wss[w]; }
        g_partial[bc] = make_float2(a, b2);
    }
}

// ============================================================================
// Kernel 2: build fused weight G[b,o,i] (fp16) and bias2[b,o].
// Finalize folded in: each block re-derives r/mu from g_partial (L2-hot).
// ============================================================================
__global__ void __launch_bounds__(256) prep_kernel(const float* __restrict__ params,
                                                   const float* __restrict__ W) {
    int bo = blockIdx.x;
    int b = bo >> 8, o = bo & 255, i = threadIdx.x;

    float2 p = g_partial[b * NC + i];
    const float invN = 1.0f / (float)NHW;
    float mu_i = p.x * invN;
    float var_i = fmaxf(p.y * invN - mu_i * mu_i, 0.f);
    float r_i = rsqrtf(var_i + 1e-5f);

    __shared__ float s1[256], s2[256];
    s1[i] = p.x; s2[i] = p.y;
    __syncthreads();
    for (int st = 128; st > 0; st >>= 1) {
        if (i < st) { s1[i] += s1[i + st]; s2[i] += s2[i + st]; }
        __syncthreads();
    }
    const float invM = 1.0f / ((float)NHW * (float)NC);
    float mub = s1[0] * invM;
    float vb = fmaxf(s2[0] * invM - mub * mub, 0.f);
    float rb = rsqrtf(vb + 1e-5f);
    __syncthreads();

    float w1 = W[o * 512 + i];
    float w2 = W[o * 512 + 256 + i];
    float gamma = params[b * 512 + o];
    g_G[(size_t)bo * NC + i] = __float2half_rn(gamma * (w1 * r_i + w2 * rb));
    float cp = w1 * r_i * mu_i + rb * mub * w2;
    s1[i] = cp;
    __syncthreads();
    for (int st = 128; st > 0; st >>= 1) {
        if (i < st) s1[i] += s1[i + st];
        __syncthreads();
    }
    if (i == 0) {
        float beta = params[b * 512 + 256 + o];
        g_bias2[bo] = beta - gamma * s1[0];
    }
}

// ============================================================================
// Kernel 3: HMMA GEMM — R5/R11 configuration (empirical optimum, untouched):
// 2 CTAs/SM, 256 threads, M=128 x N=128px x K=256, warp grid 4(M)x2(N),
// warp tile 32x64, 3-stage cp.async ring, one __syncthreads per 32-k chunk.
// mz fastest so CTA pairs sharing a pixel tile run concurrently (X via L2).
// ============================================================================
#define A_ROWS     128
#define A_STRIDE_H 264              // halves per A row (256 + 8 pad)
#define X_STRIDE_H 136              // halves per X row (128 + 8 pad)
#define KCHUNK     32
#define NCHUNKS    8
#define NSTAGES    3
#define A_BYTES    (A_ROWS * A_STRIDE_H * 2)           // 67584
#define X_BUF_BYTES (KCHUNK * X_STRIDE_H * 2)          // 8704
#define GEMM_SMEM  (A_BYTES + NSTAGES * X_BUF_BYTES)   // 93696

__global__ void __launch_bounds__(256, 2) gemm_kernel(float* __restrict__ out) {
    extern __shared__ char smem[];
    const uint32_t Asm = smem_u32(smem);
    const uint32_t Xsm = Asm + A_BYTES;

    const int tid = threadIdx.x;
    const int lane = tid & 31, wid = tid >> 5;
    const int warpM = (wid & 3) * 32;          // 4 warps over M=128
    const int warpN = (wid >> 2) * 64;         // 2 warps over N=128
    const int b = blockIdx.y;
    const int mz = blockIdx.x & 1;             // fastest dim: M half
    const int px0 = (blockIdx.x >> 1) * 128;

    // X chunk loader: 32 rows x 256B; 256 threads -> 2 x 16B each
    const int xr = tid >> 4, xseg = tid & 15;
    const __half* xbase = g_xh + ((size_t)(b * NC + xr)) * NHW + px0 + xseg * 8;
    const uint32_t xdst0 = Xsm + xr * (X_STRIDE_H * 2) + xseg * 16;
    const size_t xrow16 = (size_t)16 * NHW;

    // ---- prologue: A + chunks 0,1 ----
    {
        const __half* gsrc = g_G + (size_t)b * NC * NC + (size_t)mz * 128 * NC;
#pragma unroll
        for (int i = 0; i < 16; i++) {
            int c = tid + i * 256;
            int row = c >> 5, seg = c & 31;
            cp_async16(Asm + row * (A_STRIDE_H * 2) + seg * 16,
                       gsrc + row * 256 + seg * 8);
        }
        cp_async16(xdst0, xbase);
        cp_async16(xdst0 + 16 * (X_STRIDE_H * 2), xbase + xrow16);
        cp_commit();                                   // group: A + chunk0
        cp_async16(xdst0 + X_BUF_BYTES, xbase + (size_t)KCHUNK * NHW);
        cp_async16(xdst0 + X_BUF_BYTES + 16 * (X_STRIDE_H * 2),
                   xbase + (size_t)KCHUNK * NHW + xrow16);
        cp_commit();                                   // group: chunk1
    }

    float acc[2][8][4];
#pragma unroll
    for (int mi = 0; mi < 2; mi++)
#pragma unroll
        for (int ni = 0; ni < 8; ni++)
#pragma unroll
            for (int j = 0; j < 4; j++) acc[mi][ni][j] = 0.f;

    const int lrow = (lane & 7) + ((lane >> 3) & 1) * 8;   // 0..15
    const int lcol8 = (lane >> 4) * 8;                      // 0 or 8
    const int xlrow = ((lane >> 3) & 1) * 8 + (lane & 7);   // B-frag k row

    for (int kc = 0; kc < NCHUNKS; kc++) {
        cp_wait<1>();          // this thread's chunk-kc copies complete
        __syncthreads();       // cross-thread visibility + ring safety

        if (kc + 2 < NCHUNKS) {    // prefetch kc+2 into slot (kc+2)%3
            uint32_t d = xdst0 + ((kc + 2) % NSTAGES) * X_BUF_BYTES;
            const __half* s = xbase + (size_t)(kc + 2) * KCHUNK * NHW;
            cp_async16(d, s);
            cp_async16(d + 16 * (X_STRIDE_H * 2), s + xrow16);
        }
        cp_commit();

        const uint32_t xbuf = Xsm + (kc % NSTAGES) * X_BUF_BYTES;
#pragma unroll
        for (int ks = 0; ks < 2; ks++) {
            const int kbase = kc * KCHUNK + ks * 16;
            uint32_t af[2][4];
#pragma unroll
            for (int mi = 0; mi < 2; mi++) {
                uint32_t addr = Asm
                    + (warpM + mi * 16 + lrow) * (A_STRIDE_H * 2)
                    + (kbase + lcol8) * 2;
                ldm_x4(af[mi], addr);
            }
            uint32_t bf[8][2];
#pragma unroll
            for (int np = 0; np < 4; np++) {
                uint32_t r4[4];
                uint32_t addr = xbuf
                    + (ks * 16 + xlrow) * (X_STRIDE_H * 2)
                    + (warpN + np * 16 + lcol8) * 2;
                ldm_x4_t(r4, addr);
                bf[np * 2 + 0][0] = r4[0]; bf[np * 2 + 0][1] = r4[1];
                bf[np * 2 + 1][0] = r4[2]; bf[np * 2 + 1][1] = r4[3];
            }
#pragma unroll
            for (int mi = 0; mi < 2; mi++)
#pragma unroll
                for (int ni = 0; ni < 8; ni++)
                    mma16816(acc[mi][ni], af[mi][0], af[mi][1], af[mi][2],
                             af[mi][3], bf[ni][0], bf[ni][1]);
        }
    }

    // ---- epilogue: add bias2, store fp32 ----
#pragma unroll
    for (int mi = 0; mi < 2; mi++) {
        int chl = mz * 128 + warpM + mi * 16 + (lane >> 2);
        float bias0 = g_bias2[b * NC + chl];
        float bias1 = g_bias2[b * NC + chl + 8];
        float* row0 = out + ((size_t)(b * NC + chl)) * NHW + px0 + warpN;
        float* row1 = row0 + (size_t)8 * NHW;
#pragma unroll
        for (int ni = 0; ni < 8; ni++) {
            int co = ni * 8 + (lane & 3) * 2;
            float2 v0 = make_float2(acc[mi][ni][0] + bias0, acc[mi][ni][1] + bias0);
            float2 v1 = make_float2(acc[mi][ni][2] + bias1, acc[mi][ni][3] + bias1);
            *reinterpret_cast<float2*>(row0 + co) = v0;
            *reinterpret_cast<float2*>(row1 + co) = v1;
        }
    }
}

// ============================================================================
// Host
// ============================================================================
extern "C" void kernel_launch(void* const* d_in, const int* in_sizes, int n_in,
                              void* d_out, int out_size) {
    const float* x = (const float*)d_in[0];
    const float* params = (const float*)d_in[1];
    const float* W = (const float*)d_in[2];
    float* out = (float*)d_out;

    stats_convert<<<NB * NC, 256>>>(x);
    prep_kernel<<<NB * NC, 256>>>(params, W);

    cudaFuncSetAttribute(gemm_kernel,
                         cudaFuncAttributeMaxDynamicSharedMemorySize, GEMM_SMEM);
    gemm_kernel<<<dim3(2 * (NHW / 128), NB), 256, GEMM_SMEM>>>(out);
}